// round 6
// baseline (speedup 1.0000x reference)
#include <cuda_runtime.h>
#include <cstdint>

#define NN 4096
#define DD 1024
#define BM 128
#define BN 128
#define BK 16

typedef unsigned long long u64;

// Per-row argmin keys: (orderable(value) << 32) | col_index. min key == argmin
// with first-index tie-break, identical to jnp.argmin semantics.
__device__ u64 g_ap[NN];
__device__ u64 g_an[NN];
__device__ int g_lab[NN];
__device__ int g_is64;

// ---------------------------------------------------------------------------
// packed-f32x2 helpers (Blackwell: 2 FMAs per issue slot; ptxas never fuses)
// ---------------------------------------------------------------------------
__device__ __forceinline__ u64 splat2(float x) {
    u64 r; asm("mov.b64 %0, {%1, %1};" : "=l"(r) : "f"(x)); return r;
}
__device__ __forceinline__ u64 pack2(float lo, float hi) {
    u64 r; asm("mov.b64 %0, {%1, %2};" : "=l"(r) : "f"(lo), "f"(hi)); return r;
}
__device__ __forceinline__ void ffma2(u64& d, u64 a, u64 b) {
    asm("fma.rn.f32x2 %0, %1, %2, %0;" : "+l"(d) : "l"(a), "l"(b));
}
__device__ __forceinline__ void unpack2(u64 v, float& lo, float& hi) {
    asm("mov.b64 {%0, %1}, %2;" : "=f"(lo), "=f"(hi) : "l"(v));
}

// ---------------------------------------------------------------------------
// Detect int64-vs-int32 labels (JAX demotes int64 -> int32 without x64).
// ---------------------------------------------------------------------------
__global__ void detect_kernel(const int* __restrict__ lab32) {
    __shared__ int any;
    if (threadIdx.x == 0) any = 0;
    __syncthreads();
    int acc = 0;
    for (int i = 1 + 2 * threadIdx.x; i < 4096; i += 2 * blockDim.x)
        acc |= lab32[i];
    if (acc) atomicOr(&any, 1);
    __syncthreads();
    if (threadIdx.x == 0) g_is64 = (any == 0) ? 1 : 0;
}

__global__ void init_kernel(const int* __restrict__ lab32) {
    int i = blockIdx.x * blockDim.x + threadIdx.x;
    if (i < NN) {
        g_ap[i] = 0xFFFFFFFFFFFFFFFFull;
        g_an[i] = 0xFFFFFFFFFFFFFFFFull;
        g_lab[i] = g_is64 ? lab32[2 * i] : lab32[i];
    }
}

__device__ __forceinline__ unsigned float_order(float f) {
    unsigned u = __float_as_uint(f);
    return (u & 0x80000000u) ? ~u : (u | 0x80000000u);
}

// ---------------------------------------------------------------------------
// Symmetric fused SGEMM (FFMA2 packed) + masked argmin.
// Lower-triangular tiles only; off-diagonal tiles feed both row argmins and
// (by symmetry) column argmins. 128x128 tile, 256 threads, 8x8 micro-tile
// (stored as 8x4 f32x2 pairs along j), double-buffered smem.
// ---------------------------------------------------------------------------
__global__ __launch_bounds__(256, 2)
void gemm_argmin_sym(const float* __restrict__ X) {
    __shared__ float As[2][BK][BM + 4];
    __shared__ float Bs[2][BK][BN + 4];
    __shared__ int labA[BM];
    __shared__ int labB[BN];
    __shared__ u64 colAp[BN];
    __shared__ u64 colAn[BN];

    const int t  = threadIdx.x;
    const int tx = t & 15;
    const int ty = t >> 4;

    // ---- triangular decode: tile -> (bi, bj), bi >= bj --------------------
    const int tile = blockIdx.x;
    int bi = (int)((sqrtf(8.0f * (float)tile + 1.0f) - 1.0f) * 0.5f);
    while ((bi + 1) * (bi + 2) / 2 <= tile) bi++;
    while (bi * (bi + 1) / 2 > tile) bi--;
    const int bj = tile - bi * (bi + 1) / 2;
    const bool diag = (bi == bj);

    const int rowBase = bi * BM;
    const int colBase = bj * BN;

    if (t < BM)      labA[t]      = g_lab[rowBase + t];
    else             labB[t - BM] = g_lab[colBase + (t - BM)];
    if (t < BN) { colAp[t] = 0xFFFFFFFFFFFFFFFFull; colAn[t] = 0xFFFFFFFFFFFFFFFFull; }

    u64 acc2[8][4];
#pragma unroll
    for (int i = 0; i < 8; i++)
#pragma unroll
        for (int j = 0; j < 4; j++) acc2[i][j] = 0ull;

    const float* Arow = X + (size_t)rowBase * DD;
    const float* Brow = X + (size_t)colBase * DD;

    const int lr  = t >> 2;   // 0..63
    const int lc4 = t & 3;    // 0..3

    float4 pa0, pa1, pb0, pb1;

    // prologue: load k0 = 0
    pa0 = *(const float4*)(Arow + (size_t)lr        * DD + lc4 * 4);
    pa1 = *(const float4*)(Arow + (size_t)(lr + 64) * DD + lc4 * 4);
    pb0 = *(const float4*)(Brow + (size_t)lr        * DD + lc4 * 4);
    pb1 = *(const float4*)(Brow + (size_t)(lr + 64) * DD + lc4 * 4);

    {
        const int c = lc4 * 4;
        As[0][c + 0][lr] = pa0.x; As[0][c + 1][lr] = pa0.y;
        As[0][c + 2][lr] = pa0.z; As[0][c + 3][lr] = pa0.w;
        As[0][c + 0][lr + 64] = pa1.x; As[0][c + 1][lr + 64] = pa1.y;
        As[0][c + 2][lr + 64] = pa1.z; As[0][c + 3][lr + 64] = pa1.w;
        Bs[0][c + 0][lr] = pb0.x; Bs[0][c + 1][lr] = pb0.y;
        Bs[0][c + 2][lr] = pb0.z; Bs[0][c + 3][lr] = pb0.w;
        Bs[0][c + 0][lr + 64] = pb1.x; Bs[0][c + 1][lr + 64] = pb1.y;
        Bs[0][c + 2][lr + 64] = pb1.z; Bs[0][c + 3][lr + 64] = pb1.w;
    }
    __syncthreads();

    int buf = 0;
    for (int k0 = BK; k0 < DD; k0 += BK) {
        // issue next-tile global loads early (latency hidden under FFMA2s)
        pa0 = *(const float4*)(Arow + (size_t)lr        * DD + k0 + lc4 * 4);
        pa1 = *(const float4*)(Arow + (size_t)(lr + 64) * DD + k0 + lc4 * 4);
        pb0 = *(const float4*)(Brow + (size_t)lr        * DD + k0 + lc4 * 4);
        pb1 = *(const float4*)(Brow + (size_t)(lr + 64) * DD + k0 + lc4 * 4);

#pragma unroll
        for (int kk = 0; kk < BK; kk++) {
            float4 a0 = *(const float4*)&As[buf][kk][ty * 8];
            float4 a1 = *(const float4*)&As[buf][kk][ty * 8 + 4];
            float4 b0 = *(const float4*)&Bs[buf][kk][tx * 8];
            float4 b1 = *(const float4*)&Bs[buf][kk][tx * 8 + 4];
            u64 av[8] = {splat2(a0.x), splat2(a0.y), splat2(a0.z), splat2(a0.w),
                         splat2(a1.x), splat2(a1.y), splat2(a1.z), splat2(a1.w)};
            u64 bv[4] = {pack2(b0.x, b0.y), pack2(b0.z, b0.w),
                         pack2(b1.x, b1.y), pack2(b1.z, b1.w)};
#pragma unroll
            for (int i = 0; i < 8; i++)
#pragma unroll
                for (int jp = 0; jp < 4; jp++)
                    ffma2(acc2[i][jp], av[i], bv[jp]);
        }

        const int nb = buf ^ 1;
        const int c = lc4 * 4;
        As[nb][c + 0][lr] = pa0.x; As[nb][c + 1][lr] = pa0.y;
        As[nb][c + 2][lr] = pa0.z; As[nb][c + 3][lr] = pa0.w;
        As[nb][c + 0][lr + 64] = pa1.x; As[nb][c + 1][lr + 64] = pa1.y;
        As[nb][c + 2][lr + 64] = pa1.z; As[nb][c + 3][lr + 64] = pa1.w;
        Bs[nb][c + 0][lr] = pb0.x; Bs[nb][c + 1][lr] = pb0.y;
        Bs[nb][c + 2][lr] = pb0.z; Bs[nb][c + 3][lr] = pb0.w;
        Bs[nb][c + 0][lr + 64] = pb1.x; Bs[nb][c + 1][lr + 64] = pb1.y;
        Bs[nb][c + 2][lr + 64] = pb1.z; Bs[nb][c + 3][lr + 64] = pb1.w;
        __syncthreads();
        buf = nb;
    }

#pragma unroll
    for (int kk = 0; kk < BK; kk++) {
        float4 a0 = *(const float4*)&As[buf][kk][ty * 8];
        float4 a1 = *(const float4*)&As[buf][kk][ty * 8 + 4];
        float4 b0 = *(const float4*)&Bs[buf][kk][tx * 8];
        float4 b1 = *(const float4*)&Bs[buf][kk][tx * 8 + 4];
        u64 av[8] = {splat2(a0.x), splat2(a0.y), splat2(a0.z), splat2(a0.w),
                     splat2(a1.x), splat2(a1.y), splat2(a1.z), splat2(a1.w)};
        u64 bv[4] = {pack2(b0.x, b0.y), pack2(b0.z, b0.w),
                     pack2(b1.x, b1.y), pack2(b1.z, b1.w)};
#pragma unroll
        for (int i = 0; i < 8; i++)
#pragma unroll
            for (int jp = 0; jp < 4; jp++)
                ffma2(acc2[i][jp], av[i], bv[jp]);
    }

    // ---- unpack accumulators ---------------------------------------------
    float acc[8][8];
#pragma unroll
    for (int i = 0; i < 8; i++)
#pragma unroll
        for (int jp = 0; jp < 4; jp++)
            unpack2(acc2[i][jp], acc[i][2 * jp], acc[i][2 * jp + 1]);

    // ---- row epilogue: rows of tile bi, candidate cols of tile bj ---------
#pragma unroll
    for (int i = 0; i < 8; i++) {
        const int r   = rowBase + ty * 8 + i;
        const int lri = labA[ty * 8 + i];
        u64 kap = 0xFFFFFFFFFFFFFFFFull;
        u64 kan = 0xFFFFFFFFFFFFFFFFull;
#pragma unroll
        for (int j = 0; j < 8; j++) {
            const int c    = colBase + tx * 8 + j;
            const bool same = (lri == labB[tx * 8 + j]);
            const float v  = acc[i][j];
            const float vap = v + ((same && (r != c)) ? 0.0f : 2.0f);
            const float van = v + (same ? 2.0f : 0.0f);
            u64 k1 = ((u64)float_order(vap) << 32) | (unsigned)c;
            u64 k2 = ((u64)float_order(van) << 32) | (unsigned)c;
            kap = (k1 < kap) ? k1 : kap;
            kan = (k2 < kan) ? k2 : kan;
        }
#pragma unroll
        for (int off = 8; off >= 1; off >>= 1) {
            u64 o1 = __shfl_xor_sync(0xffffffffu, kap, off);
            u64 o2 = __shfl_xor_sync(0xffffffffu, kan, off);
            kap = (o1 < kap) ? o1 : kap;
            kan = (o2 < kan) ? o2 : kan;
        }
        if (tx == 0) {
            atomicMin(&g_ap[r], kap);
            atomicMin(&g_an[r], kan);
        }
    }

    // ---- column epilogue (off-diagonal only) via symmetry -----------------
    if (!diag) {
        __syncthreads();
#pragma unroll
        for (int j = 0; j < 8; j++) {
            const int lcj = labB[tx * 8 + j];
            u64 kap = 0xFFFFFFFFFFFFFFFFull;
            u64 kan = 0xFFFFFFFFFFFFFFFFull;
#pragma unroll
            for (int i = 0; i < 8; i++) {
                const int r    = rowBase + ty * 8 + i;  // candidate index
                const bool same = (labA[ty * 8 + i] == lcj);
                const float v  = acc[i][j];
                const float vap = v + (same ? 0.0f : 2.0f);
                const float van = v + (same ? 2.0f : 0.0f);
                u64 k1 = ((u64)float_order(vap) << 32) | (unsigned)r;
                u64 k2 = ((u64)float_order(van) << 32) | (unsigned)r;
                kap = (k1 < kap) ? k1 : kap;
                kan = (k2 < kan) ? k2 : kan;
            }
            atomicMin(&colAp[tx * 8 + j], kap);
            atomicMin(&colAn[tx * 8 + j], kan);
        }
        __syncthreads();
        if (t < BN) {
            atomicMin(&g_ap[colBase + t], colAp[t]);
            atomicMin(&g_an[colBase + t], colAn[t]);
        }
    }
}

// ---------------------------------------------------------------------------
// Gather: out[0][r][:] = X[id_ap[r]], out[1][r][:] = X[id_an[r]]
// ---------------------------------------------------------------------------
__global__ void gather_kernel(const float* __restrict__ X, float* __restrict__ out) {
    const int r     = blockIdx.x;
    const int which = blockIdx.y;
    const unsigned idx =
        (unsigned)((which ? g_an[r] : g_ap[r]) & 0xFFFFFFFFull);
    const float4* src = (const float4*)(X + (size_t)idx * DD);
    float4* dst = (float4*)(out + ((size_t)which * NN + r) * DD);
    for (int i = threadIdx.x; i < DD / 4; i += blockDim.x)
        dst[i] = src[i];
}

extern "C" void kernel_launch(void* const* d_in, const int* in_sizes, int n_in,
                              void* d_out, int out_size) {
    const float* X   = (const float*)d_in[0];
    const int*   lab = (const int*)d_in[1];
    float*       out = (float*)d_out;

    detect_kernel<<<1, 256>>>(lab);
    init_kernel<<<16, 256>>>(lab);
    const int ntiles = (NN / BM) * (NN / BM + 1) / 2;  // 32*33/2 = 528
    gemm_argmin_sym<<<ntiles, 256>>>(X);
    gather_kernel<<<dim3(NN, 2), 256>>>(X, out);
}

// round 8
// speedup vs baseline: 1.7312x; 1.7312x over previous
#include <cuda_runtime.h>
#include <cuda_fp16.h>
#include <cstdint>

#define NN 4096
#define DD 1024
#define BM 128
#define BN 128
#define KCH 32            // K per chunk (fp32 elems)
#define NCHUNK (DD / KCH)

typedef unsigned long long u64;

__device__ u64 g_ap[NN];
__device__ u64 g_an[NN];
__device__ int g_lab[NN];
__device__ int g_is64;

// ---------------------------------------------------------------------------
__global__ void detect_kernel(const int* __restrict__ lab32) {
    __shared__ int any;
    if (threadIdx.x == 0) any = 0;
    __syncthreads();
    int acc = 0;
    for (int i = 1 + 2 * threadIdx.x; i < 4096; i += 2 * blockDim.x)
        acc |= lab32[i];
    if (acc) atomicOr(&any, 1);
    __syncthreads();
    if (threadIdx.x == 0) g_is64 = (any == 0) ? 1 : 0;
}

__global__ void init_kernel(const int* __restrict__ lab32) {
    int i = blockIdx.x * blockDim.x + threadIdx.x;
    if (i < NN) {
        g_ap[i] = 0xFFFFFFFFFFFFFFFFull;
        g_an[i] = 0xFFFFFFFFFFFFFFFFull;
        g_lab[i] = g_is64 ? lab32[2 * i] : lab32[i];
    }
}

__device__ __forceinline__ unsigned float_order(float f) {
    unsigned u = __float_as_uint(f);
    return (u & 0x80000000u) ? ~u : (u | 0x80000000u);
}

__device__ __forceinline__ uint32_t smem_u32(const void* p) {
    uint32_t a;
    asm("{ .reg .u64 t; cvta.to.shared.u64 t, %1; cvt.u32.u64 %0, t; }"
        : "=r"(a) : "l"(p));
    return a;
}

// ldmatrix x4 / x2 (non-trans), fp16 mma m16n8k16 with fp32 accumulate
#define LDSM4(r0, r1, r2, r3, addr) \
    asm volatile("ldmatrix.sync.aligned.m8n8.x4.shared.b16 {%0,%1,%2,%3}, [%4];" \
        : "=r"(r0), "=r"(r1), "=r"(r2), "=r"(r3) : "r"(addr))
#define LDSM2(r0, r1, addr) \
    asm volatile("ldmatrix.sync.aligned.m8n8.x2.shared.b16 {%0,%1}, [%2];" \
        : "=r"(r0), "=r"(r1) : "r"(addr))
#define MMA16816(d, a, b) \
    asm volatile("mma.sync.aligned.m16n8k16.row.col.f32.f16.f16.f32 " \
        "{%0,%1,%2,%3}, {%4,%5,%6,%7}, {%8,%9}, {%0,%1,%2,%3};" \
        : "+f"((d)[0]), "+f"((d)[1]), "+f"((d)[2]), "+f"((d)[3]) \
        : "r"((a)[0]), "r"((a)[1]), "r"((a)[2]), "r"((a)[3]), "r"((b)[0]), "r"((b)[1]))

// Tile smem layout: per 128-byte row: [hi: quads 0-3][lo: quads 4-7], quad =
// 16B = 8 fp16 (k-span 8). Physical quad = (logical ^ (row & 7)).
__device__ __forceinline__ uint32_t tile_addr(uint32_t base, int row, int q) {
    return base + row * 128 + ((q ^ (row & 7)) << 4);
}

#define TILE_BYTES (BM * 128)            // 16 KB per tile (hi+lo)
#define BUF_BYTES  (2 * TILE_BYTES)      // A + B
// dynamic smem: 2 buffers = 64 KB

// ---------------------------------------------------------------------------
__global__ __launch_bounds__(256, 1)
void gemm_argmin_mma(const float* __restrict__ X) {
    extern __shared__ char smem[];
    const uint32_t sb = smem_u32(smem);

    __shared__ int labA[BM], labB[BN];
    __shared__ u64 rowAp[BM], rowAn[BM], colAp[BN], colAn[BN];

    const int t    = threadIdx.x;
    const int lane = t & 31;
    const int w    = t >> 5;

    // triangular decode: tile -> (bi, bj), bi >= bj
    const int tile = blockIdx.x;
    int bi = (int)((sqrtf(8.0f * (float)tile + 1.0f) - 1.0f) * 0.5f);
    while ((bi + 1) * (bi + 2) / 2 <= tile) bi++;
    while (bi * (bi + 1) / 2 > tile) bi--;
    const int bj = tile - bi * (bi + 1) / 2;
    const bool diag = (bi == bj);
    const int rowBase = bi * BM;
    const int colBase = bj * BN;

    if (t < BM) {
        labA[t] = g_lab[rowBase + t];
        labB[t] = g_lab[colBase + t];
        rowAp[t] = 0xFFFFFFFFFFFFFFFFull; rowAn[t] = 0xFFFFFFFFFFFFFFFFull;
        colAp[t] = 0xFFFFFFFFFFFFFFFFull; colAn[t] = 0xFFFFFFFFFFFFFFFFull;
    }

    // loader mapping: row = t>>1 (0..127), kh = t&1 (k 16 each)
    const int lrow = t >> 1;
    const int kh   = t & 1;
    const float* Asrc = X + (size_t)(rowBase + lrow) * DD + kh * 16;
    const float* Bsrc = X + (size_t)(colBase + lrow) * DD + kh * 16;

    float acc[4][4][4];
#pragma unroll
    for (int mt = 0; mt < 4; mt++)
#pragma unroll
        for (int nt = 0; nt < 4; nt++)
#pragma unroll
            for (int e = 0; e < 4; e++) acc[mt][nt][e] = 0.0f;

    // warp tiling: wr = w>>2 (0-1) rows wr*64.., wc = w&3 cols wc*32..
    const int wr = w >> 2;
    const int wc = w & 3;

    // staging registers
    float4 sa[4], sbv[4];

    // split+store helper (lambda-free, macro-ish via function)
    auto split_store = [&](uint32_t tbase, const float4* s) {
        // 16 fp32 -> hi/lo fp16, 2 quads each
        unsigned short h[16], l[16];
#pragma unroll
        for (int g = 0; g < 4; g++) {
            float f[4] = {s[g].x, s[g].y, s[g].z, s[g].w};
#pragma unroll
            for (int e = 0; e < 4; e++) {
                __half hh = __float2half_rn(f[e]);
                float r = f[e] - __half2float(hh);
                __half ll = __float2half_rn(r);
                h[g * 4 + e] = __half_as_ushort(hh);
                l[g * 4 + e] = __half_as_ushort(ll);
            }
        }
#pragma unroll
        for (int q = 0; q < 2; q++) {   // quads within this thread's k-half
            uint4 H, L;
            const unsigned short* hp = h + q * 8;
            const unsigned short* lp = l + q * 8;
            H.x = hp[0] | (hp[1] << 16); H.y = hp[2] | (hp[3] << 16);
            H.z = hp[4] | (hp[5] << 16); H.w = hp[6] | (hp[7] << 16);
            L.x = lp[0] | (lp[1] << 16); L.y = lp[2] | (lp[3] << 16);
            L.z = lp[4] | (lp[5] << 16); L.w = lp[6] | (lp[7] << 16);
            const int kq = kh * 2 + q;
            *(uint4*)(smem + (tile_addr(0, lrow, kq) )     + (tbase - 0)) = H;  // hi: quad kq
            *(uint4*)(smem + (tile_addr(0, lrow, 4 + kq) ) + (tbase - 0)) = L;  // lo: quad 4+kq
        }
    };

    // prologue: chunk 0
#pragma unroll
    for (int g = 0; g < 4; g++) { sa[g] = *(const float4*)(Asrc + g * 4); sbv[g] = *(const float4*)(Bsrc + g * 4); }
    split_store(0, sa);                 // A tile buf0 at offset 0
    split_store(TILE_BYTES, sbv);       // B tile buf0
    __syncthreads();

    for (int c = 0; c < NCHUNK; c++) {
        const int buf = c & 1;
        const uint32_t abase = sb + buf * BUF_BYTES;
        const uint32_t bbase = abase + TILE_BYTES;

        if (c + 1 < NCHUNK) {
            const float* An = Asrc + (c + 1) * KCH;
            const float* Bn = Bsrc + (c + 1) * KCH;
#pragma unroll
            for (int g = 0; g < 4; g++) { sa[g] = *(const float4*)(An + g * 4); sbv[g] = *(const float4*)(Bn + g * 4); }
        }

        // ---- MMA over this chunk: 2 k-steps of 16 ------------------------
#pragma unroll
        for (int ks = 0; ks < 2; ks++) {
            uint32_t ah[4][4], al[4][4], bh[4][2], bl[4][2];
            // A frags: matrix m: row = mtbase + (m&1)*8 + lane&7, quad = ks*2 + (m>>1)
            const int arow = wr * 64 + (lane & 7) + ((lane >> 3) & 1) * 8;
            const int akq  = ks * 2 + (lane >> 4);
#pragma unroll
            for (int mt = 0; mt < 4; mt++) {
                uint32_t ad = tile_addr(abase, arow + mt * 16, akq);
                LDSM4(ah[mt][0], ah[mt][1], ah[mt][2], ah[mt][3], ad);
                uint32_t ad2 = tile_addr(abase, arow + mt * 16, 4 + akq);
                LDSM4(al[mt][0], al[mt][1], al[mt][2], al[mt][3], ad2);
            }
            // B frags: x2, lanes 0-15: matrix m = (lane>>3)&1, row n = nbase + lane&7
            const int bl_  = lane & 15;
            const int brow = wc * 32 + (bl_ & 7);
            const int bkq  = ks * 2 + (bl_ >> 3);
#pragma unroll
            for (int nt = 0; nt < 4; nt++) {
                uint32_t bd = tile_addr(bbase, brow + nt * 8, bkq);
                LDSM2(bh[nt][0], bh[nt][1], bd);
                uint32_t bd2 = tile_addr(bbase, brow + nt * 8, 4 + bkq);
                LDSM2(bl[nt][0], bl[nt][1], bd2);
            }
            // 3 combos: hh, hl, lh
#pragma unroll
            for (int mt = 0; mt < 4; mt++)
#pragma unroll
                for (int nt = 0; nt < 4; nt++) {
                    MMA16816(acc[mt][nt], ah[mt], bh[nt]);
                    MMA16816(acc[mt][nt], ah[mt], bl[nt]);
                    MMA16816(acc[mt][nt], al[mt], bh[nt]);
                }
        }

        if (c + 1 < NCHUNK) {
            const uint32_t nb = (buf ^ 1) * BUF_BYTES;
            split_store(nb, sa);
            split_store(nb + TILE_BYTES, sbv);
        }
        __syncthreads();
    }

    // ---- epilogue ---------------------------------------------------------
    // acc frag: e0:(rl, cq) e1:(rl, cq+1) e2:(rl+8, cq) e3:(rl+8, cq+1)
    // rl = lane>>2, cq = (lane&3)*2 (within m16n8 tile)
    const int rl = lane >> 2;
    const int cq = (lane & 3) * 2;

    // row argmins
#pragma unroll
    for (int mt = 0; mt < 4; mt++)
#pragma unroll
        for (int rh = 0; rh < 2; rh++) {
            const int lr_ = wr * 64 + mt * 16 + rh * 8 + rl;
            const int r   = rowBase + lr_;
            const int lri = labA[lr_];
            u64 kap = 0xFFFFFFFFFFFFFFFFull, kan = 0xFFFFFFFFFFFFFFFFull;
#pragma unroll
            for (int nt = 0; nt < 4; nt++)
#pragma unroll
                for (int cp = 0; cp < 2; cp++) {
                    const int jc = wc * 32 + nt * 8 + cq + cp;
                    const int ccol = colBase + jc;
                    const bool same = (lri == labB[jc]);
                    const float v = acc[mt][nt][rh * 2 + cp];
                    const float vap = v + ((same && (r != ccol)) ? 0.0f : 2.0f);
                    const float van = v + (same ? 2.0f : 0.0f);
                    u64 k1 = ((u64)float_order(vap) << 32) | (unsigned)ccol;
                    u64 k2 = ((u64)float_order(van) << 32) | (unsigned)ccol;
                    kap = (k1 < kap) ? k1 : kap;
                    kan = (k2 < kan) ? k2 : kan;
                }
#pragma unroll
            for (int off = 1; off <= 2; off <<= 1) {
                u64 o1 = __shfl_xor_sync(0xffffffffu, kap, off);
                u64 o2 = __shfl_xor_sync(0xffffffffu, kan, off);
                kap = (o1 < kap) ? o1 : kap;
                kan = (o2 < kan) ? o2 : kan;
            }
            if ((lane & 3) == 0) {
                atomicMin(&rowAp[lr_], kap);
                atomicMin(&rowAn[lr_], kan);
            }
        }

    // column argmins (off-diagonal tiles only), candidates indexed by row
    if (!diag) {
#pragma unroll
        for (int nt = 0; nt < 4; nt++)
#pragma unroll
            for (int cp = 0; cp < 2; cp++) {
                const int jc  = wc * 32 + nt * 8 + cq + cp;
                const int lcj = labB[jc];
                u64 kap = 0xFFFFFFFFFFFFFFFFull, kan = 0xFFFFFFFFFFFFFFFFull;
#pragma unroll
                for (int mt = 0; mt < 4; mt++)
#pragma unroll
                    for (int rh = 0; rh < 2; rh++) {
                        const int r = rowBase + wr * 64 + mt * 16 + rh * 8 + rl;
                        const bool same = (labA[wr * 64 + mt * 16 + rh * 8 + rl] == lcj);
                        const float v = acc[mt][nt][rh * 2 + cp];
                        const float vap = v + (same ? 0.0f : 2.0f);
                        const float van = v + (same ? 2.0f : 0.0f);
                        u64 k1 = ((u64)float_order(vap) << 32) | (unsigned)r;
                        u64 k2 = ((u64)float_order(van) << 32) | (unsigned)r;
                        kap = (k1 < kap) ? k1 : kap;
                        kan = (k2 < kan) ? k2 : kan;
                    }
#pragma unroll
                for (int off = 4; off <= 16; off <<= 1) {
                    u64 o1 = __shfl_xor_sync(0xffffffffu, kap, off);
                    u64 o2 = __shfl_xor_sync(0xffffffffu, kan, off);
                    kap = (o1 < kap) ? o1 : kap;
                    kan = (o2 < kan) ? o2 : kan;
                }
                if (rl == 0) {
                    atomicMin(&colAp[jc], kap);
                    atomicMin(&colAn[jc], kan);
                }
            }
    }
    __syncthreads();

    if (t < BM) {
        atomicMin(&g_ap[rowBase + t], rowAp[t]);
        atomicMin(&g_an[rowBase + t], rowAn[t]);
        if (!diag) {
            atomicMin(&g_ap[colBase + t], colAp[t]);
            atomicMin(&g_an[colBase + t], colAn[t]);
        }
    }
}

// ---------------------------------------------------------------------------
__global__ void gather_kernel(const float* __restrict__ X, float* __restrict__ out) {
    const int r     = blockIdx.x;
    const int which = blockIdx.y;
    const unsigned idx =
        (unsigned)((which ? g_an[r] : g_ap[r]) & 0xFFFFFFFFull);
    const float4* src = (const float4*)(X + (size_t)idx * DD);
    float4* dst = (float4*)(out + ((size_t)which * NN + r) * DD);
    for (int i = threadIdx.x; i < DD / 4; i += blockDim.x)
        dst[i] = src[i];
}

extern "C" void kernel_launch(void* const* d_in, const int* in_sizes, int n_in,
                              void* d_out, int out_size) {
    const float* X   = (const float*)d_in[0];
    const int*   lab = (const int*)d_in[1];
    float*       out = (float*)d_out;

    const int smem_bytes = 2 * BUF_BYTES;  // 64 KB
    cudaFuncSetAttribute(gemm_argmin_mma,
                         cudaFuncAttributeMaxDynamicSharedMemorySize, smem_bytes);

    detect_kernel<<<1, 256>>>(lab);
    init_kernel<<<16, 256>>>(lab);
    const int ntiles = (NN / BM) * (NN / BM + 1) / 2;  // 528
    gemm_argmin_mma<<<ntiles, 256, smem_bytes>>>(X);
    gather_kernel<<<dim3(NN, 2), 256>>>(X, out);
}

// round 9
// speedup vs baseline: 2.2118x; 1.2776x over previous
#include <cuda_runtime.h>
#include <cuda_fp16.h>
#include <cstdint>

#define NN 4096
#define DD 1024
#define BM 128
#define BN 128
#define KCH 32            // K per chunk (elems)
#define NCHUNK (DD / KCH)
#define NSTAGE 4

typedef unsigned long long u64;

__device__ u64 g_ap[NN];
__device__ u64 g_an[NN];
__device__ int g_lab[NN];
__device__ int g_is64;
__device__ __half g_hi[NN * DD];   // 8 MB
__device__ __half g_lo[NN * DD];   // 8 MB

// ---------------------------------------------------------------------------
__global__ void detect_kernel(const int* __restrict__ lab32) {
    __shared__ int any;
    if (threadIdx.x == 0) any = 0;
    __syncthreads();
    int acc = 0;
    for (int i = 1 + 2 * threadIdx.x; i < 4096; i += 2 * blockDim.x)
        acc |= lab32[i];
    if (acc) atomicOr(&any, 1);
    __syncthreads();
    if (threadIdx.x == 0) g_is64 = (any == 0) ? 1 : 0;
}

__global__ void init_kernel(const int* __restrict__ lab32) {
    int i = blockIdx.x * blockDim.x + threadIdx.x;
    if (i < NN) {
        g_ap[i] = 0xFFFFFFFFFFFFFFFFull;
        g_an[i] = 0xFFFFFFFFFFFFFFFFull;
        g_lab[i] = g_is64 ? lab32[2 * i] : lab32[i];
    }
}

// fp32 -> (hi, lo) fp16 split, whole matrix, once.
__global__ void split_kernel(const float* __restrict__ X) {
    const int t = blockIdx.x * blockDim.x + threadIdx.x;   // 0 .. NN*DD/4-1
    float4 v = ((const float4*)X)[t];
    float f[4] = {v.x, v.y, v.z, v.w};
    __half h[4], l[4];
#pragma unroll
    for (int e = 0; e < 4; e++) {
        h[e] = __float2half_rn(f[e]);
        l[e] = __float2half_rn(f[e] - __half2float(h[e]));
    }
    ((uint2*)g_hi)[t] = *(uint2*)h;
    ((uint2*)g_lo)[t] = *(uint2*)l;
}

__device__ __forceinline__ unsigned float_order(float f) {
    unsigned u = __float_as_uint(f);
    return (u & 0x80000000u) ? ~u : (u | 0x80000000u);
}

__device__ __forceinline__ uint32_t smem_u32(const void* p) {
    uint32_t a;
    asm("{ .reg .u64 t; cvta.to.shared.u64 t, %1; cvt.u32.u64 %0, t; }"
        : "=r"(a) : "l"(p));
    return a;
}

#define LDSM4(r0, r1, r2, r3, addr) \
    asm volatile("ldmatrix.sync.aligned.m8n8.x4.shared.b16 {%0,%1,%2,%3}, [%4];" \
        : "=r"(r0), "=r"(r1), "=r"(r2), "=r"(r3) : "r"(addr))
#define LDSM2(r0, r1, addr) \
    asm volatile("ldmatrix.sync.aligned.m8n8.x2.shared.b16 {%0,%1}, [%2];" \
        : "=r"(r0), "=r"(r1) : "r"(addr))
#define MMA16816(d, a, b) \
    asm volatile("mma.sync.aligned.m16n8k16.row.col.f32.f16.f16.f32 " \
        "{%0,%1,%2,%3}, {%4,%5,%6,%7}, {%8,%9}, {%0,%1,%2,%3};" \
        : "+f"((d)[0]), "+f"((d)[1]), "+f"((d)[2]), "+f"((d)[3]) \
        : "r"((a)[0]), "r"((a)[1]), "r"((a)[2]), "r"((a)[3]), "r"((b)[0]), "r"((b)[1]))
#define CP_ASYNC16(dst, src) \
    asm volatile("cp.async.cg.shared.global [%0], [%1], 16;" :: "r"(dst), "l"(src))
#define CP_COMMIT() asm volatile("cp.async.commit_group;" ::: "memory")
#define CP_WAIT2()  asm volatile("cp.async.wait_group 2;" ::: "memory")

// Tile smem layout: per 128-byte row: [hi: quads 0-3][lo: quads 4-7], quad =
// 16B = 8 fp16 (k-span 8). Physical quad = (logical ^ (row & 7)).
__device__ __forceinline__ uint32_t tile_addr(uint32_t base, int row, int q) {
    return base + row * 128 + ((q ^ (row & 7)) << 4);
}

#define TILE_BYTES (BM * 128)            // 16 KB  (hi+lo for one 128x32 tile)
#define STAGE_BYTES (2 * TILE_BYTES)     // A + B = 32 KB
#define SMEM_TOTAL (NSTAGE * STAGE_BYTES) // 128 KB

// ---------------------------------------------------------------------------
__global__ __launch_bounds__(256, 1)
void gemm_argmin_mma(const float* __restrict__ X) {
    extern __shared__ char smem[];
    const uint32_t sb = smem_u32(smem);

    __shared__ int labA[BM], labB[BN];
    __shared__ u64 rowAp[BM], rowAn[BM], colAp[BN], colAn[BN];

    const int t    = threadIdx.x;
    const int lane = t & 31;
    const int w    = t >> 5;

    // triangular decode: tile -> (bi, bj), bi >= bj
    const int tile = blockIdx.x;
    int bi = (int)((sqrtf(8.0f * (float)tile + 1.0f) - 1.0f) * 0.5f);
    while ((bi + 1) * (bi + 2) / 2 <= tile) bi++;
    while (bi * (bi + 1) / 2 > tile) bi--;
    const int bj = tile - bi * (bi + 1) / 2;
    const bool diag = (bi == bj);
    const int rowBase = bi * BM;
    const int colBase = bj * BN;

    if (t < BM) {
        labA[t] = g_lab[rowBase + t];
        labB[t] = g_lab[colBase + t];
        rowAp[t] = 0xFFFFFFFFFFFFFFFFull; rowAn[t] = 0xFFFFFFFFFFFFFFFFull;
        colAp[t] = 0xFFFFFFFFFFFFFFFFull; colAn[t] = 0xFFFFFFFFFFFFFFFFull;
    }

    // -------- async loader: 8 quads (16B) per thread per stage -------------
    // id = t + i*256 in [0,2048): tile = id>>10 (0=A,1=B), row = (id>>3)&127,
    // q = id&7 (q<4: hi quad q ; q>=4: lo quad q-4)
    auto issue_stage = [&](int c, int slot) {
        const uint32_t sbase = sb + slot * STAGE_BYTES;
#pragma unroll
        for (int i = 0; i < 8; i++) {
            const int id  = t + i * 256;
            const int tl  = id >> 10;
            const int row = (id >> 3) & 127;
            const int q   = id & 7;
            const int gr  = (tl ? colBase : rowBase) + row;
            const __half* src = (q < 4 ? g_hi : g_lo)
                                + (size_t)gr * DD + c * KCH + (q & 3) * 8;
            const uint32_t dst = tile_addr(sbase + tl * TILE_BYTES, row, q);
            CP_ASYNC16(dst, src);
        }
        CP_COMMIT();
    };

    float acc[4][4][4];
#pragma unroll
    for (int mt = 0; mt < 4; mt++)
#pragma unroll
        for (int nt = 0; nt < 4; nt++)
#pragma unroll
            for (int e = 0; e < 4; e++) acc[mt][nt][e] = 0.0f;

    const int wr = w >> 2;   // 0-1: rows wr*64..
    const int wc = w & 3;    // 0-3: cols wc*32..

    // prologue: stages 0..2
    issue_stage(0, 0);
    issue_stage(1, 1);
    issue_stage(2, 2);

    for (int c = 0; c < NCHUNK; c++) {
        CP_WAIT2();               // stage c landed
        __syncthreads();          // all warps done with slot (c-1)%4 reads
        if (c + 3 < NCHUNK) issue_stage(c + 3, (c + 3) & 3);
        else CP_COMMIT();         // keep group accounting uniform

        const uint32_t abase = sb + (c & 3) * STAGE_BYTES;
        const uint32_t bbase = abase + TILE_BYTES;

#pragma unroll
        for (int ks = 0; ks < 2; ks++) {
            uint32_t ah[4][4], al[4][4], bh[4][2], bl[4][2];
            const int arow = wr * 64 + (lane & 7) + ((lane >> 3) & 1) * 8;
            const int akq  = ks * 2 + (lane >> 4);
#pragma unroll
            for (int mt = 0; mt < 4; mt++) {
                uint32_t ad = tile_addr(abase, arow + mt * 16, akq);
                LDSM4(ah[mt][0], ah[mt][1], ah[mt][2], ah[mt][3], ad);
                uint32_t ad2 = tile_addr(abase, arow + mt * 16, 4 + akq);
                LDSM4(al[mt][0], al[mt][1], al[mt][2], al[mt][3], ad2);
            }
            const int bl_  = lane & 15;
            const int brow = wc * 32 + (bl_ & 7);
            const int bkq  = ks * 2 + (bl_ >> 3);
#pragma unroll
            for (int nt = 0; nt < 4; nt++) {
                uint32_t bd = tile_addr(bbase, brow + nt * 8, bkq);
                LDSM2(bh[nt][0], bh[nt][1], bd);
                uint32_t bd2 = tile_addr(bbase, brow + nt * 8, 4 + bkq);
                LDSM2(bl[nt][0], bl[nt][1], bd2);
            }
#pragma unroll
            for (int mt = 0; mt < 4; mt++)
#pragma unroll
                for (int nt = 0; nt < 4; nt++) {
                    MMA16816(acc[mt][nt], ah[mt], bh[nt]);
                    MMA16816(acc[mt][nt], ah[mt], bl[nt]);
                    MMA16816(acc[mt][nt], al[mt], bh[nt]);
                }
        }
    }

    // ---- epilogue (identical to R8) ---------------------------------------
    const int rl = lane >> 2;
    const int cq = (lane & 3) * 2;

#pragma unroll
    for (int mt = 0; mt < 4; mt++)
#pragma unroll
        for (int rh = 0; rh < 2; rh++) {
            const int lr_ = wr * 64 + mt * 16 + rh * 8 + rl;
            const int r   = rowBase + lr_;
            const int lri = labA[lr_];
            u64 kap = 0xFFFFFFFFFFFFFFFFull, kan = 0xFFFFFFFFFFFFFFFFull;
#pragma unroll
            for (int nt = 0; nt < 4; nt++)
#pragma unroll
                for (int cp = 0; cp < 2; cp++) {
                    const int jc = wc * 32 + nt * 8 + cq + cp;
                    const int ccol = colBase + jc;
                    const bool same = (lri == labB[jc]);
                    const float v = acc[mt][nt][rh * 2 + cp];
                    const float vap = v + ((same && (r != ccol)) ? 0.0f : 2.0f);
                    const float van = v + (same ? 2.0f : 0.0f);
                    u64 k1 = ((u64)float_order(vap) << 32) | (unsigned)ccol;
                    u64 k2 = ((u64)float_order(van) << 32) | (unsigned)ccol;
                    kap = (k1 < kap) ? k1 : kap;
                    kan = (k2 < kan) ? k2 : kan;
                }
#pragma unroll
            for (int off = 1; off <= 2; off <<= 1) {
                u64 o1 = __shfl_xor_sync(0xffffffffu, kap, off);
                u64 o2 = __shfl_xor_sync(0xffffffffu, kan, off);
                kap = (o1 < kap) ? o1 : kap;
                kan = (o2 < kan) ? o2 : kan;
            }
            if ((lane & 3) == 0) {
                atomicMin(&rowAp[lr_], kap);
                atomicMin(&rowAn[lr_], kan);
            }
        }

    if (!diag) {
#pragma unroll
        for (int nt = 0; nt < 4; nt++)
#pragma unroll
            for (int cp = 0; cp < 2; cp++) {
                const int jc  = wc * 32 + nt * 8 + cq + cp;
                const int lcj = labB[jc];
                u64 kap = 0xFFFFFFFFFFFFFFFFull, kan = 0xFFFFFFFFFFFFFFFFull;
#pragma unroll
                for (int mt = 0; mt < 4; mt++)
#pragma unroll
                    for (int rh = 0; rh < 2; rh++) {
                        const int lr_ = wr * 64 + mt * 16 + rh * 8 + rl;
                        const int r = rowBase + lr_;
                        const bool same = (labA[lr_] == lcj);
                        const float v = acc[mt][nt][rh * 2 + cp];
                        const float vap = v + (same ? 0.0f : 2.0f);
                        const float van = v + (same ? 2.0f : 0.0f);
                        u64 k1 = ((u64)float_order(vap) << 32) | (unsigned)r;
                        u64 k2 = ((u64)float_order(van) << 32) | (unsigned)r;
                        kap = (k1 < kap) ? k1 : kap;
                        kan = (k2 < kan) ? k2 : kan;
                    }
#pragma unroll
                for (int off = 4; off <= 16; off <<= 1) {
                    u64 o1 = __shfl_xor_sync(0xffffffffu, kap, off);
                    u64 o2 = __shfl_xor_sync(0xffffffffu, kan, off);
                    kap = (o1 < kap) ? o1 : kap;
                    kan = (o2 < kan) ? o2 : kan;
                }
                if (rl == 0) {
                    atomicMin(&colAp[jc], kap);
                    atomicMin(&colAn[jc], kan);
                }
            }
    }
    __syncthreads();

    if (t < BM) {
        atomicMin(&g_ap[rowBase + t], rowAp[t]);
        atomicMin(&g_an[rowBase + t], rowAn[t]);
        if (!diag) {
            atomicMin(&g_ap[colBase + t], colAp[t]);
            atomicMin(&g_an[colBase + t], colAn[t]);
        }
    }
}

// ---------------------------------------------------------------------------
__global__ void gather_kernel(const float* __restrict__ X, float* __restrict__ out) {
    const int r     = blockIdx.x;
    const int which = blockIdx.y;
    const unsigned idx =
        (unsigned)((which ? g_an[r] : g_ap[r]) & 0xFFFFFFFFull);
    const float4* src = (const float4*)(X + (size_t)idx * DD);
    float4* dst = (float4*)(out + ((size_t)which * NN + r) * DD);
    for (int i = threadIdx.x; i < DD / 4; i += blockDim.x)
        dst[i] = src[i];
}

extern "C" void kernel_launch(void* const* d_in, const int* in_sizes, int n_in,
                              void* d_out, int out_size) {
    const float* X   = (const float*)d_in[0];
    const int*   lab = (const int*)d_in[1];
    float*       out = (float*)d_out;

    cudaFuncSetAttribute(gemm_argmin_mma,
                         cudaFuncAttributeMaxDynamicSharedMemorySize, SMEM_TOTAL);

    detect_kernel<<<1, 256>>>(lab);
    init_kernel<<<16, 256>>>(lab);
    split_kernel<<<(NN * DD / 4) / 256, 256>>>(X);
    const int ntiles = (NN / BM) * (NN / BM + 1) / 2;  // 528
    gemm_argmin_mma<<<ntiles, 256, SMEM_TOTAL>>>(X);
    gather_kernel<<<dim3(NN, 2), 256>>>(X, out);
}

// round 12
// speedup vs baseline: 2.2193x; 1.0034x over previous
#include <cuda_runtime.h>
#include <cuda_fp16.h>
#include <cstdint>

#define NN 4096
#define DD 1024
#define BM 128
#define BN 128
#define KCH 32            // K per chunk (elems)
#define NCHUNK (DD / KCH)
#define NSTAGE 4

typedef unsigned long long u64;

__device__ u64 g_ap[NN];
__device__ u64 g_an[NN];
__device__ int g_lab[NN];
__device__ int g_is64;
__device__ __half g_hi[NN * DD];   // 8 MB
__device__ __half g_lo[NN * DD];   // 8 MB

// ---------------------------------------------------------------------------
__global__ void detect_kernel(const int* __restrict__ lab32) {
    __shared__ int any;
    if (threadIdx.x == 0) any = 0;
    __syncthreads();
    int acc = 0;
    for (int i = 1 + 2 * threadIdx.x; i < 4096; i += 2 * blockDim.x)
        acc |= lab32[i];
    if (acc) atomicOr(&any, 1);
    __syncthreads();
    if (threadIdx.x == 0) g_is64 = (any == 0) ? 1 : 0;
}

__global__ void init_kernel(const int* __restrict__ lab32) {
    int i = blockIdx.x * blockDim.x + threadIdx.x;
    if (i < NN) {
        g_ap[i] = 0xFFFFFFFFFFFFFFFFull;
        g_an[i] = 0xFFFFFFFFFFFFFFFFull;
        g_lab[i] = g_is64 ? lab32[2 * i] : lab32[i];
    }
}

// fp32 -> (hi, lo) fp16 split, whole matrix, once.
__global__ void split_kernel(const float* __restrict__ X) {
    const int t = blockIdx.x * blockDim.x + threadIdx.x;   // 0 .. NN*DD/4-1
    float4 v = ((const float4*)X)[t];
    float f[4] = {v.x, v.y, v.z, v.w};
    __half h[4], l[4];
#pragma unroll
    for (int e = 0; e < 4; e++) {
        h[e] = __float2half_rn(f[e]);
        l[e] = __float2half_rn(f[e] - __half2float(h[e]));
    }
    ((uint2*)g_hi)[t] = *(uint2*)h;
    ((uint2*)g_lo)[t] = *(uint2*)l;
}

__device__ __forceinline__ unsigned float_order(float f) {
    unsigned u = __float_as_uint(f);
    return (u & 0x80000000u) ? ~u : (u | 0x80000000u);
}

__device__ __forceinline__ uint32_t smem_u32(const void* p) {
    uint32_t a;
    asm("{ .reg .u64 t; cvta.to.shared.u64 t, %1; cvt.u32.u64 %0, t; }"
        : "=r"(a) : "l"(p));
    return a;
}

#define LDSM4(r0, r1, r2, r3, addr) \
    asm volatile("ldmatrix.sync.aligned.m8n8.x4.shared.b16 {%0,%1,%2,%3}, [%4];" \
        : "=r"(r0), "=r"(r1), "=r"(r2), "=r"(r3) : "r"(addr))
#define LDSM2(r0, r1, addr) \
    asm volatile("ldmatrix.sync.aligned.m8n8.x2.shared.b16 {%0,%1}, [%2];" \
        : "=r"(r0), "=r"(r1) : "r"(addr))
#define MMA16816(d, a, b) \
    asm volatile("mma.sync.aligned.m16n8k16.row.col.f32.f16.f16.f32 " \
        "{%0,%1,%2,%3}, {%4,%5,%6,%7}, {%8,%9}, {%0,%1,%2,%3};" \
        : "+f"((d)[0]), "+f"((d)[1]), "+f"((d)[2]), "+f"((d)[3]) \
        : "r"((a)[0]), "r"((a)[1]), "r"((a)[2]), "r"((a)[3]), "r"((b)[0]), "r"((b)[1]))
#define CP_ASYNC16(dst, src) \
    asm volatile("cp.async.cg.shared.global [%0], [%1], 16;" :: "r"(dst), "l"(src))
#define CP_COMMIT() asm volatile("cp.async.commit_group;" ::: "memory")
#define CP_WAIT2()  asm volatile("cp.async.wait_group 2;" ::: "memory")

// Tile smem layout: per 128-byte row: [hi: quads 0-3][lo: quads 4-7], quad =
// 16B = 8 fp16 (k-span 8). Physical quad = (logical ^ (row & 7)).
__device__ __forceinline__ uint32_t tile_addr(uint32_t base, int row, int q) {
    return base + row * 128 + ((q ^ (row & 7)) << 4);
}

#define TILE_BYTES (BM * 128)             // 16 KB  (hi+lo for one 128x32 tile)
#define STAGE_BYTES (2 * TILE_BYTES)      // A + B = 32 KB
#define SMEM_TOTAL (NSTAGE * STAGE_BYTES) // 128 KB

// ---------------------------------------------------------------------------
__global__ __launch_bounds__(256, 1)
void gemm_argmin_mma(const float* __restrict__ X) {
    extern __shared__ char smem[];
    const uint32_t sb = smem_u32(smem);

    __shared__ int labA[BM], labB[BN];
    __shared__ u64 rowAp[BM], rowAn[BM], colAp[BN], colAn[BN];

    const int t    = threadIdx.x;
    const int lane = t & 31;
    const int w    = t >> 5;

    // triangular decode: tile -> (bi, bj), bi >= bj
    const int tile = blockIdx.x;
    int bi = (int)((sqrtf(8.0f * (float)tile + 1.0f) - 1.0f) * 0.5f);
    while ((bi + 1) * (bi + 2) / 2 <= tile) bi++;
    while (bi * (bi + 1) / 2 > tile) bi--;
    const int bj = tile - bi * (bi + 1) / 2;
    const bool diag = (bi == bj);
    const int rowBase = bi * BM;
    const int colBase = bj * BN;

    if (t < BM) {
        labA[t] = g_lab[rowBase + t];
        labB[t] = g_lab[colBase + t];
        rowAp[t] = 0xFFFFFFFFFFFFFFFFull; rowAn[t] = 0xFFFFFFFFFFFFFFFFull;
        colAp[t] = 0xFFFFFFFFFFFFFFFFull; colAn[t] = 0xFFFFFFFFFFFFFFFFull;
    }

    // -------- async loader: 8 quads (16B) per thread per stage -------------
    auto issue_stage = [&](int c, int slot) {
        const uint32_t sbase = sb + slot * STAGE_BYTES;
#pragma unroll
        for (int i = 0; i < 8; i++) {
            const int id  = t + i * 256;
            const int tl  = id >> 10;
            const int row = (id >> 3) & 127;
            const int q   = id & 7;
            const int gr  = (tl ? colBase : rowBase) + row;
            const __half* src = (q < 4 ? g_hi : g_lo)
                                + (size_t)gr * DD + c * KCH + (q & 3) * 8;
            const uint32_t dst = tile_addr(sbase + tl * TILE_BYTES, row, q);
            CP_ASYNC16(dst, src);
        }
        CP_COMMIT();
    };

    float acc[4][4][4];
#pragma unroll
    for (int mt = 0; mt < 4; mt++)
#pragma unroll
        for (int nt = 0; nt < 4; nt++)
#pragma unroll
            for (int e = 0; e < 4; e++) acc[mt][nt][e] = 0.0f;

    const int wr = w >> 2;   // 0-1: rows wr*64..
    const int wc = w & 3;    // 0-3: cols wc*32..

    // prologue: stages 0..2
    issue_stage(0, 0);
    issue_stage(1, 1);
    issue_stage(2, 2);

    for (int c = 0; c < NCHUNK; c++) {
        CP_WAIT2();               // stage c landed
        __syncthreads();          // all warps done with slot (c-1)%4 reads
        if (c + 3 < NCHUNK) issue_stage(c + 3, (c + 3) & 3);
        else CP_COMMIT();         // keep group accounting uniform

        const uint32_t abase = sb + (c & 3) * STAGE_BYTES;
        const uint32_t bbase = abase + TILE_BYTES;

#pragma unroll
        for (int ks = 0; ks < 2; ks++) {
            uint32_t ah[4][4], al[4][4], bh[4][2], bl[4][2];
            const int arow = wr * 64 + (lane & 7) + ((lane >> 3) & 1) * 8;
            const int akq  = ks * 2 + (lane >> 4);
#pragma unroll
            for (int mt = 0; mt < 4; mt++) {
                uint32_t ad = tile_addr(abase, arow + mt * 16, akq);
                LDSM4(ah[mt][0], ah[mt][1], ah[mt][2], ah[mt][3], ad);
                uint32_t ad2 = tile_addr(abase, arow + mt * 16, 4 + akq);
                LDSM4(al[mt][0], al[mt][1], al[mt][2], al[mt][3], ad2);
            }
            const int bl_  = lane & 15;
            const int brow = wc * 32 + (bl_ & 7);
            const int bkq  = ks * 2 + (bl_ >> 3);
#pragma unroll
            for (int nt = 0; nt < 4; nt++) {
                uint32_t bd = tile_addr(bbase, brow + nt * 8, bkq);
                LDSM2(bh[nt][0], bh[nt][1], bd);
                uint32_t bd2 = tile_addr(bbase, brow + nt * 8, 4 + bkq);
                LDSM2(bl[nt][0], bl[nt][1], bd2);
            }
            // combo-outer ordering: 16 independent accumulators between
            // dependent MMAs -> tensor-pipe dependency stalls eliminated.
            // Per-acc arrival order remains hh, hl, lh (bit-identical values).
#pragma unroll
            for (int mt = 0; mt < 4; mt++)
#pragma unroll
                for (int nt = 0; nt < 4; nt++)
                    MMA16816(acc[mt][nt], ah[mt], bh[nt]);
#pragma unroll
            for (int mt = 0; mt < 4; mt++)
#pragma unroll
                for (int nt = 0; nt < 4; nt++)
                    MMA16816(acc[mt][nt], ah[mt], bl[nt]);
#pragma unroll
            for (int mt = 0; mt < 4; mt++)
#pragma unroll
                for (int nt = 0; nt < 4; nt++)
                    MMA16816(acc[mt][nt], al[mt], bh[nt]);
        }
    }

    // ---- epilogue (identical to R9) ---------------------------------------
    const int rl = lane >> 2;
    const int cq = (lane & 3) * 2;

#pragma unroll
    for (int mt = 0; mt < 4; mt++)
#pragma unroll
        for (int rh = 0; rh < 2; rh++) {
            const int lr_ = wr * 64 + mt * 16 + rh * 8 + rl;
            const int r   = rowBase + lr_;
            const int lri = labA[lr_];
            u64 kap = 0xFFFFFFFFFFFFFFFFull, kan = 0xFFFFFFFFFFFFFFFFull;
#pragma unroll
            for (int nt = 0; nt < 4; nt++)
#pragma unroll
                for (int cp = 0; cp < 2; cp++) {
                    const int jc = wc * 32 + nt * 8 + cq + cp;
                    const int ccol = colBase + jc;
                    const bool same = (lri == labB[jc]);
                    const float v = acc[mt][nt][rh * 2 + cp];
                    const float vap = v + ((same && (r != ccol)) ? 0.0f : 2.0f);
                    const float van = v + (same ? 2.0f : 0.0f);
                    u64 k1 = ((u64)float_order(vap) << 32) | (unsigned)ccol;
                    u64 k2 = ((u64)float_order(van) << 32) | (unsigned)ccol;
                    kap = (k1 < kap) ? k1 : kap;
                    kan = (k2 < kan) ? k2 : kan;
                }
#pragma unroll
            for (int off = 1; off <= 2; off <<= 1) {
                u64 o1 = __shfl_xor_sync(0xffffffffu, kap, off);
                u64 o2 = __shfl_xor_sync(0xffffffffu, kan, off);
                kap = (o1 < kap) ? o1 : kap;
                kan = (o2 < kan) ? o2 : kan;
            }
            if ((lane & 3) == 0) {
                atomicMin(&rowAp[lr_], kap);
                atomicMin(&rowAn[lr_], kan);
            }
        }

    if (!diag) {
#pragma unroll
        for (int nt = 0; nt < 4; nt++)
#pragma unroll
            for (int cp = 0; cp < 2; cp++) {
                const int jc  = wc * 32 + nt * 8 + cq + cp;
                const int lcj = labB[jc];
                u64 kap = 0xFFFFFFFFFFFFFFFFull, kan = 0xFFFFFFFFFFFFFFFFull;
#pragma unroll
                for (int mt = 0; mt < 4; mt++)
#pragma unroll
                    for (int rh = 0; rh < 2; rh++) {
                        const int lr_ = wr * 64 + mt * 16 + rh * 8 + rl;
                        const int r = rowBase + lr_;
                        const bool same = (labA[lr_] == lcj);
                        const float v = acc[mt][nt][rh * 2 + cp];
                        const float vap = v + (same ? 0.0f : 2.0f);
                        const float van = v + (same ? 2.0f : 0.0f);
                        u64 k1 = ((u64)float_order(vap) << 32) | (unsigned)r;
                        u64 k2 = ((u64)float_order(van) << 32) | (unsigned)r;
                        kap = (k1 < kap) ? k1 : kap;
                        kan = (k2 < kan) ? k2 : kan;
                    }
#pragma unroll
                for (int off = 4; off <= 16; off <<= 1) {
                    u64 o1 = __shfl_xor_sync(0xffffffffu, kap, off);
                    u64 o2 = __shfl_xor_sync(0xffffffffu, kan, off);
                    kap = (o1 < kap) ? o1 : kap;
                    kan = (o2 < kan) ? o2 : kan;
                }
                if (rl == 0) {
                    atomicMin(&colAp[jc], kap);
                    atomicMin(&colAn[jc], kan);
                }
            }
    }
    __syncthreads();

    if (t < BM) {
        atomicMin(&g_ap[rowBase + t], rowAp[t]);
        atomicMin(&g_an[rowBase + t], rowAn[t]);
        if (!diag) {
            atomicMin(&g_ap[colBase + t], colAp[t]);
            atomicMin(&g_an[colBase + t], colAn[t]);
        }
    }
}

// ---------------------------------------------------------------------------
__global__ void gather_kernel(const float* __restrict__ X, float* __restrict__ out) {
    const int r     = blockIdx.x;
    const int which = blockIdx.y;
    const unsigned idx =
        (unsigned)((which ? g_an[r] : g_ap[r]) & 0xFFFFFFFFull);
    const float4* src = (const float4*)(X + (size_t)idx * DD);
    float4* dst = (float4*)(out + ((size_t)which * NN + r) * DD);
    for (int i = threadIdx.x; i < DD / 4; i += blockDim.x)
        dst[i] = src[i];
}

extern "C" void kernel_launch(void* const* d_in, const int* in_sizes, int n_in,
                              void* d_out, int out_size) {
    const float* X   = (const float*)d_in[0];
    const int*   lab = (const int*)d_in[1];
    float*       out = (float*)d_out;

    cudaFuncSetAttribute(gemm_argmin_mma,
                         cudaFuncAttributeMaxDynamicSharedMemorySize, SMEM_TOTAL);

    detect_kernel<<<1, 256>>>(lab);
    init_kernel<<<16, 256>>>(lab);
    split_kernel<<<(NN * DD / 4) / 256, 256>>>(X);
    const int ntiles = (NN / BM) * (NN / BM + 1) / 2;  // 528
    gemm_argmin_mma<<<ntiles, 256, SMEM_TOTAL>>>(X);
    gather_kernel<<<dim3(NN, 2), 256>>>(X, out);
}

// round 14
// speedup vs baseline: 2.2334x; 1.0063x over previous
#include <cuda_runtime.h>
#include <cuda_fp16.h>
#include <cstdint>

#define NN 4096
#define DD 1024
#define BM 128
#define BN 128
#define KCH 32            // K per chunk (elems)
#define NCHUNK (DD / KCH)
#define NSTAGE 4
#define NTHREADS 512

typedef unsigned long long u64;

__device__ u64 g_ap[NN];
__device__ u64 g_an[NN];
__device__ int g_lab[NN];
__device__ int g_is64;
__device__ __half g_hi[NN * DD];   // 8 MB
__device__ __half g_lo[NN * DD];   // 8 MB

// ---------------------------------------------------------------------------
__global__ void detect_kernel(const int* __restrict__ lab32) {
    __shared__ int any;
    if (threadIdx.x == 0) any = 0;
    __syncthreads();
    int acc = 0;
    for (int i = 1 + 2 * threadIdx.x; i < 4096; i += 2 * blockDim.x)
        acc |= lab32[i];
    if (acc) atomicOr(&any, 1);
    __syncthreads();
    if (threadIdx.x == 0) g_is64 = (any == 0) ? 1 : 0;
}

__global__ void init_kernel(const int* __restrict__ lab32) {
    int i = blockIdx.x * blockDim.x + threadIdx.x;
    if (i < NN) {
        g_ap[i] = 0xFFFFFFFFFFFFFFFFull;
        g_an[i] = 0xFFFFFFFFFFFFFFFFull;
        g_lab[i] = g_is64 ? lab32[2 * i] : lab32[i];
    }
}

// fp32 -> (hi, lo) fp16 split, whole matrix, once.
__global__ void split_kernel(const float* __restrict__ X) {
    const int t = blockIdx.x * blockDim.x + threadIdx.x;   // 0 .. NN*DD/4-1
    float4 v = ((const float4*)X)[t];
    float f[4] = {v.x, v.y, v.z, v.w};
    __half h[4], l[4];
#pragma unroll
    for (int e = 0; e < 4; e++) {
        h[e] = __float2half_rn(f[e]);
        l[e] = __float2half_rn(f[e] - __half2float(h[e]));
    }
    ((uint2*)g_hi)[t] = *(uint2*)h;
    ((uint2*)g_lo)[t] = *(uint2*)l;
}

__device__ __forceinline__ unsigned float_order(float f) {
    unsigned u = __float_as_uint(f);
    return (u & 0x80000000u) ? ~u : (u | 0x80000000u);
}

__device__ __forceinline__ uint32_t smem_u32(const void* p) {
    uint32_t a;
    asm("{ .reg .u64 t; cvta.to.shared.u64 t, %1; cvt.u32.u64 %0, t; }"
        : "=r"(a) : "l"(p));
    return a;
}

#define LDSM4(r0, r1, r2, r3, addr) \
    asm volatile("ldmatrix.sync.aligned.m8n8.x4.shared.b16 {%0,%1,%2,%3}, [%4];" \
        : "=r"(r0), "=r"(r1), "=r"(r2), "=r"(r3) : "r"(addr))
#define LDSM2(r0, r1, addr) \
    asm volatile("ldmatrix.sync.aligned.m8n8.x2.shared.b16 {%0,%1}, [%2];" \
        : "=r"(r0), "=r"(r1) : "r"(addr))
#define MMA16816(d, a, b) \
    asm volatile("mma.sync.aligned.m16n8k16.row.col.f32.f16.f16.f32 " \
        "{%0,%1,%2,%3}, {%4,%5,%6,%7}, {%8,%9}, {%0,%1,%2,%3};" \
        : "+f"((d)[0]), "+f"((d)[1]), "+f"((d)[2]), "+f"((d)[3]) \
        : "r"((a)[0]), "r"((a)[1]), "r"((a)[2]), "r"((a)[3]), "r"((b)[0]), "r"((b)[1]))
#define CP_ASYNC16(dst, src) \
    asm volatile("cp.async.cg.shared.global [%0], [%1], 16;" :: "r"(dst), "l"(src))
#define CP_COMMIT() asm volatile("cp.async.commit_group;" ::: "memory")
#define CP_WAIT2()  asm volatile("cp.async.wait_group 2;" ::: "memory")

// Tile smem layout: per 128-byte row: [hi: quads 0-3][lo: quads 4-7], quad =
// 16B = 8 fp16 (k-span 8). Physical quad = (logical ^ (row & 7)).
__device__ __forceinline__ uint32_t tile_addr(uint32_t base, int row, int q) {
    return base + row * 128 + ((q ^ (row & 7)) << 4);
}

#define TILE_BYTES (BM * 128)             // 16 KB  (hi+lo for one 128x32 tile)
#define STAGE_BYTES (2 * TILE_BYTES)      // A + B = 32 KB
#define SMEM_TOTAL (NSTAGE * STAGE_BYTES) // 128 KB

// ---------------------------------------------------------------------------
// 512 threads / 16 warps, warp tile 32x32 -> 4 warps per SMSP (latency cover).
// ---------------------------------------------------------------------------
__global__ __launch_bounds__(NTHREADS, 1)
void gemm_argmin_mma(const float* __restrict__ X) {
    extern __shared__ char smem[];
    const uint32_t sb = smem_u32(smem);

    __shared__ int labA[BM], labB[BN];
    __shared__ u64 rowAp[BM], rowAn[BM], colAp[BN], colAn[BN];

    const int t    = threadIdx.x;
    const int lane = t & 31;
    const int w    = t >> 5;

    // triangular decode: tile -> (bi, bj), bi >= bj
    const int tile = blockIdx.x;
    int bi = (int)((sqrtf(8.0f * (float)tile + 1.0f) - 1.0f) * 0.5f);
    while ((bi + 1) * (bi + 2) / 2 <= tile) bi++;
    while (bi * (bi + 1) / 2 > tile) bi--;
    const int bj = tile - bi * (bi + 1) / 2;
    const bool diag = (bi == bj);
    const int rowBase = bi * BM;
    const int colBase = bj * BN;

    if (t < BM) {
        labA[t] = g_lab[rowBase + t];
        labB[t] = g_lab[colBase + t];
        rowAp[t] = 0xFFFFFFFFFFFFFFFFull; rowAn[t] = 0xFFFFFFFFFFFFFFFFull;
        colAp[t] = 0xFFFFFFFFFFFFFFFFull; colAn[t] = 0xFFFFFFFFFFFFFFFFull;
    }

    // -------- async loader: 4 quads (16B) per thread per stage -------------
    // id = t + i*512 in [0,2048): tl = id>>10 (0=A,1=B), row = (id>>3)&127,
    // q = id&7 (q<4: hi quad q ; q>=4: lo quad q-4)
    auto issue_stage = [&](int c, int slot) {
        const uint32_t sbase = sb + slot * STAGE_BYTES;
#pragma unroll
        for (int i = 0; i < 4; i++) {
            const int id  = t + i * NTHREADS;
            const int tl  = id >> 10;
            const int row = (id >> 3) & 127;
            const int q   = id & 7;
            const int gr  = (tl ? colBase : rowBase) + row;
            const __half* src = (q < 4 ? g_hi : g_lo)
                                + (size_t)gr * DD + c * KCH + (q & 3) * 8;
            const uint32_t dst = tile_addr(sbase + tl * TILE_BYTES, row, q);
            CP_ASYNC16(dst, src);
        }
        CP_COMMIT();
    };

    float acc[2][4][4];
#pragma unroll
    for (int mt = 0; mt < 2; mt++)
#pragma unroll
        for (int nt = 0; nt < 4; nt++)
#pragma unroll
            for (int e = 0; e < 4; e++) acc[mt][nt][e] = 0.0f;

    const int wr = w >> 2;   // 0-3: rows wr*32..
    const int wc = w & 3;    // 0-3: cols wc*32..

    // prologue: stages 0..2
    issue_stage(0, 0);
    issue_stage(1, 1);
    issue_stage(2, 2);

    for (int c = 0; c < NCHUNK; c++) {
        CP_WAIT2();               // stage c landed
        __syncthreads();          // all warps done with slot (c-1)%4 reads
        if (c + 3 < NCHUNK) issue_stage(c + 3, (c + 3) & 3);
        else CP_COMMIT();         // keep group accounting uniform

        const uint32_t abase = sb + (c & 3) * STAGE_BYTES;
        const uint32_t bbase = abase + TILE_BYTES;

#pragma unroll
        for (int ks = 0; ks < 2; ks++) {
            uint32_t ah[2][4], al[2][4], bh[4][2], bl[4][2];
            const int arow = wr * 32 + (lane & 7) + ((lane >> 3) & 1) * 8;
            const int akq  = ks * 2 + (lane >> 4);
#pragma unroll
            for (int mt = 0; mt < 2; mt++) {
                uint32_t ad = tile_addr(abase, arow + mt * 16, akq);
                LDSM4(ah[mt][0], ah[mt][1], ah[mt][2], ah[mt][3], ad);
                uint32_t ad2 = tile_addr(abase, arow + mt * 16, 4 + akq);
                LDSM4(al[mt][0], al[mt][1], al[mt][2], al[mt][3], ad2);
            }
            const int bl_  = lane & 15;
            const int brow = wc * 32 + (bl_ & 7);
            const int bkq  = ks * 2 + (bl_ >> 3);
#pragma unroll
            for (int nt = 0; nt < 4; nt++) {
                uint32_t bd = tile_addr(bbase, brow + nt * 8, bkq);
                LDSM2(bh[nt][0], bh[nt][1], bd);
                uint32_t bd2 = tile_addr(bbase, brow + nt * 8, 4 + bkq);
                LDSM2(bl[nt][0], bl[nt][1], bd2);
            }
            // per-acc combo order stays hh, hl, lh (bit-identical values)
#pragma unroll
            for (int mt = 0; mt < 2; mt++)
#pragma unroll
                for (int nt = 0; nt < 4; nt++)
                    MMA16816(acc[mt][nt], ah[mt], bh[nt]);
#pragma unroll
            for (int mt = 0; mt < 2; mt++)
#pragma unroll
                for (int nt = 0; nt < 4; nt++)
                    MMA16816(acc[mt][nt], ah[mt], bl[nt]);
#pragma unroll
            for (int mt = 0; mt < 2; mt++)
#pragma unroll
                for (int nt = 0; nt < 4; nt++)
                    MMA16816(acc[mt][nt], al[mt], bh[nt]);
        }
    }

    // ---- epilogue ---------------------------------------------------------
    const int rl = lane >> 2;
    const int cq = (lane & 3) * 2;

#pragma unroll
    for (int mt = 0; mt < 2; mt++)
#pragma unroll
        for (int rh = 0; rh < 2; rh++) {
            const int lr_ = wr * 32 + mt * 16 + rh * 8 + rl;
            const int r   = rowBase + lr_;
            const int lri = labA[lr_];
            u64 kap = 0xFFFFFFFFFFFFFFFFull, kan = 0xFFFFFFFFFFFFFFFFull;
#pragma unroll
            for (int nt = 0; nt < 4; nt++)
#pragma unroll
                for (int cp = 0; cp < 2; cp++) {
                    const int jc = wc * 32 + nt * 8 + cq + cp;
                    const int ccol = colBase + jc;
                    const bool same = (lri == labB[jc]);
                    const float v = acc[mt][nt][rh * 2 + cp];
                    const float vap = v + ((same && (r != ccol)) ? 0.0f : 2.0f);
                    const float van = v + (same ? 2.0f : 0.0f);
                    u64 k1 = ((u64)float_order(vap) << 32) | (unsigned)ccol;
                    u64 k2 = ((u64)float_order(van) << 32) | (unsigned)ccol;
                    kap = (k1 < kap) ? k1 : kap;
                    kan = (k2 < kan) ? k2 : kan;
                }
#pragma unroll
            for (int off = 1; off <= 2; off <<= 1) {
                u64 o1 = __shfl_xor_sync(0xffffffffu, kap, off);
                u64 o2 = __shfl_xor_sync(0xffffffffu, kan, off);
                kap = (o1 < kap) ? o1 : kap;
                kan = (o2 < kan) ? o2 : kan;
            }
            if ((lane & 3) == 0) {
                atomicMin(&rowAp[lr_], kap);
                atomicMin(&rowAn[lr_], kan);
            }
        }

    if (!diag) {
#pragma unroll
        for (int nt = 0; nt < 4; nt++)
#pragma unroll
            for (int cp = 0; cp < 2; cp++) {
                const int jc  = wc * 32 + nt * 8 + cq + cp;
                const int lcj = labB[jc];
                u64 kap = 0xFFFFFFFFFFFFFFFFull, kan = 0xFFFFFFFFFFFFFFFFull;
#pragma unroll
                for (int mt = 0; mt < 2; mt++)
#pragma unroll
                    for (int rh = 0; rh < 2; rh++) {
                        const int lr_ = wr * 32 + mt * 16 + rh * 8 + rl;
                        const int r = rowBase + lr_;
                        const bool same = (labA[lr_] == lcj);
                        const float v = acc[mt][nt][rh * 2 + cp];
                        const float vap = v + (same ? 0.0f : 2.0f);
                        const float van = v + (same ? 2.0f : 0.0f);
                        u64 k1 = ((u64)float_order(vap) << 32) | (unsigned)r;
                        u64 k2 = ((u64)float_order(van) << 32) | (unsigned)r;
                        kap = (k1 < kap) ? k1 : kap;
                        kan = (k2 < kan) ? k2 : kan;
                    }
#pragma unroll
                for (int off = 4; off <= 16; off <<= 1) {
                    u64 o1 = __shfl_xor_sync(0xffffffffu, kap, off);
                    u64 o2 = __shfl_xor_sync(0xffffffffu, kan, off);
                    kap = (o1 < kap) ? o1 : kap;
                    kan = (o2 < kan) ? o2 : kan;
                }
                if (rl == 0) {
                    atomicMin(&colAp[jc], kap);
                    atomicMin(&colAn[jc], kan);
                }
            }
    }
    __syncthreads();

    if (t < BM) {
        atomicMin(&g_ap[rowBase + t], rowAp[t]);
        atomicMin(&g_an[rowBase + t], rowAn[t]);
        if (!diag) {
            atomicMin(&g_ap[colBase + t], colAp[t]);
            atomicMin(&g_an[colBase + t], colAn[t]);
        }
    }
}

// ---------------------------------------------------------------------------
__global__ void gather_kernel(const float* __restrict__ X, float* __restrict__ out) {
    const int r     = blockIdx.x;
    const int which = blockIdx.y;
    const unsigned idx =
        (unsigned)((which ? g_an[r] : g_ap[r]) & 0xFFFFFFFFull);
    const float4* src = (const float4*)(X + (size_t)idx * DD);
    float4* dst = (float4*)(out + ((size_t)which * NN + r) * DD);
    for (int i = threadIdx.x; i < DD / 4; i += blockDim.x)
        dst[i] = src[i];
}

extern "C" void kernel_launch(void* const* d_in, const int* in_sizes, int n_in,
                              void* d_out, int out_size) {
    const float* X   = (const float*)d_in[0];
    const int*   lab = (const int*)d_in[1];
    float*       out = (float*)d_out;

    cudaFuncSetAttribute(gemm_argmin_mma,
                         cudaFuncAttributeMaxDynamicSharedMemorySize, SMEM_TOTAL);

    detect_kernel<<<1, 256>>>(lab);
    init_kernel<<<16, 256>>>(lab);
    split_kernel<<<(NN * DD / 4) / 256, 256>>>(X);
    const int ntiles = (NN / BM) * (NN / BM + 1) / 2;  // 528
    gemm_argmin_mma<<<ntiles, NTHREADS, SMEM_TOTAL>>>(X);
    gather_kernel<<<dim3(NN, 2), 256>>>(X, out);
}